// round 13
// baseline (speedup 1.0000x reference)
#include <cuda_runtime.h>
#include <cuda_fp16.h>

#define Nn    6144
#define EMB   256
#define HID   128
#define EPOS  98304
#define ENEG  24576
#define EPOT  262144
#define SIGMA 100.0f
#define TDEL  0.1f

#define TOT     (ENEG + EPOS + EPOT)   // 385024
#define NLOSS   (ENEG + EPOS)          // 122880

// role layout (single kernel, 128 threads/block)
#define TR_BLKS   24                   // weight transpose
#define MLP_BLKS  192                  // 96 row-tiles x 2 branches
#define EDGE_BLKS (TOT / 16)           // 24064 (16 edges per block)
#define NEG_B16   (ENEG / 16)          // 1536
#define PN_B16    (NLOSS / 16)         // 7680
#define GRID      (TR_BLKS + MLP_BLKS + EDGE_BLKS)

// fp16 weights (transposed, n-major)
__device__ __half hW1t[2][HID * EMB];
__device__ __half hW2t[2][HID * HID];
// latents: per node [link 0..127 | aa 128..255] = 512B
__device__ __half g_lat[Nn * 256];
// spread loss accumulators (128B stride)
__device__ float g_loss[64 * 32];
// dependency + replay-reset counters (zero-initialized at module load,
// restored to zero by the resets below on every run)
__device__ unsigned w_done, m_done, e_passed, g_done;

// ---------------------------------------------------------------------------
__device__ __forceinline__ void mma16816(float* c, const unsigned* a,
                                         unsigned b0, unsigned b1) {
    asm volatile(
        "mma.sync.aligned.m16n8k16.row.col.f32.f16.f16.f32 "
        "{%0,%1,%2,%3}, {%4,%5,%6,%7}, {%8,%9}, {%0,%1,%2,%3};"
        : "+f"(c[0]), "+f"(c[1]), "+f"(c[2]), "+f"(c[3])
        : "r"(a[0]), "r"(a[1]), "r"(a[2]), "r"(a[3]), "r"(b0), "r"(b1));
}

__device__ __forceinline__ unsigned cvt2(float2 f) {
    __half2 h = __floats2half2_rn(f.x, f.y);
    return *(unsigned*)&h;
}

__device__ __forceinline__ float fsigmoid(float x) {
    return 1.0f / (1.0f + __expf(-x));
}

__device__ __forceinline__ float dot16h(uint4 u, uint4 v) {
    float d = 0.0f;
    float2 a, c;
    a = __half22float2(*(const __half2*)&u.x); c = __half22float2(*(const __half2*)&v.x);
    d += a.x * c.x + a.y * c.y;
    a = __half22float2(*(const __half2*)&u.y); c = __half22float2(*(const __half2*)&v.y);
    d += a.x * c.x + a.y * c.y;
    a = __half22float2(*(const __half2*)&u.z); c = __half22float2(*(const __half2*)&v.z);
    d += a.x * c.x + a.y * c.y;
    a = __half22float2(*(const __half2*)&u.w); c = __half22float2(*(const __half2*)&v.w);
    d += a.x * c.x + a.y * c.y;
    return d;
}

// spin until *p >= target (volatile L2 reads + backoff), then acquire-fence
__device__ __forceinline__ void spin_wait(volatile unsigned* p, unsigned target) {
    while (*p < target) __nanosleep(100);
    __threadfence();   // acquire: order subsequent loads after the flag read
}

#define SH_PITCH 136
// shared: union of transpose tile (64x65 fp32 = 16640B) and mlp sH (64*136*2 = 17408B)
#define SMEM_BYTES 17408

// ---------------------------------------------------------------------------
__global__ __launch_bounds__(128) void fused_kernel(
    const float* __restrict__ emb,
    const float* __restrict__ aa,
    const float* __restrict__ fdiff,
    const float* __restrict__ W1l, const float* __restrict__ b1l,
    const float* __restrict__ W2l, const float* __restrict__ b2l,
    const float* __restrict__ W1a, const float* __restrict__ b1a,
    const float* __restrict__ W2a, const float* __restrict__ b2a,
    const float* __restrict__ emb_w,
    const float* __restrict__ struct_w,
    const int*   __restrict__ pos_e,
    const int*   __restrict__ neg_e,
    const int*   __restrict__ pot_e,
    float* __restrict__ out)
{
    __shared__ __align__(16) char smem_raw[SMEM_BYTES];
    const int bid = blockIdx.x;
    const int tid = threadIdx.x;

    // =====================================================================
    // ROLE 1: weight transpose fp32 -> fp16 n-major (blocks 0..23)
    // =====================================================================
    if (bid < TR_BLKS) {
        float (*sT)[65] = (float(*)[65])smem_raw;

        if (bid == 0 && tid < 64) g_loss[tid * 32] = 0.0f;

        const float* Wsrc;
        __half* Wdst;
        int kstride_src, kstride_dst, k0, n0;
        if (bid < 16) {                       // W1: 256(k) x 128(n), 8 tiles/branch
            int br = bid >> 3, t = bid & 7;
            int tk = t >> 1, tn = t & 1;
            Wsrc = br ? W1a : W1l;
            Wdst = hW1t[br];
            kstride_src = HID;  kstride_dst = EMB;
            k0 = tk * 64;  n0 = tn * 64;
        } else {                              // W2: 128 x 128, 4 tiles/branch
            int c = bid - 16;
            int br = c >> 2, t = c & 3;
            int tk = t >> 1, tn = t & 1;
            Wsrc = br ? W2a : W2l;
            Wdst = hW2t[br];
            kstride_src = HID;  kstride_dst = HID;
            k0 = tk * 64;  n0 = tn * 64;
        }

        // load 64x64 fp32 tile (coalesced rows)
        #pragma unroll
        for (int it = 0; it < 8; it++) {
            int idx = it * 128 + tid;
            int row = idx >> 4, c4 = (idx & 15) * 4;
            float4 v = *(const float4*)(Wsrc + (size_t)(k0 + row) * kstride_src + n0 + c4);
            sT[row][c4]     = v.x; sT[row][c4 + 1] = v.y;
            sT[row][c4 + 2] = v.z; sT[row][c4 + 3] = v.w;
        }
        __syncthreads();

        // store transposed (coalesced in k), fp16
        #pragma unroll
        for (int it = 0; it < 8; it++) {
            int idx = it * 128 + tid;
            int n = idx >> 4, k4 = (idx & 15) * 4;
            float f0 = sT[k4][n],     f1 = sT[k4 + 1][n];
            float f2 = sT[k4 + 2][n], f3 = sT[k4 + 3][n];
            __half2 h0 = __floats2half2_rn(f0, f1);
            __half2 h1 = __floats2half2_rn(f2, f3);
            uint2 st; st.x = *(unsigned*)&h0; st.y = *(unsigned*)&h1;
            *(uint2*)(Wdst + (size_t)(n0 + n) * kstride_dst + k0 + k4) = st;
        }

        // release
        __threadfence();
        __syncthreads();
        if (tid == 0) atomicAdd(&w_done, 1u);
        return;
    }

    // =====================================================================
    // ROLE 2: MLP (blocks 24..215): 64 rows x 128 cols per block
    // =====================================================================
    if (bid < TR_BLKS + MLP_BLKS) {
        __half* sH = (__half*)smem_raw;

        // wait for weights
        if (tid == 0) spin_wait(&w_done, TR_BLKS);
        __syncthreads();

        const int mb = bid - TR_BLKS;
        const int branch = mb & 1;
        const int xt = mb >> 1;
        const float* B1 = branch ? b1a : b1l;
        const float* B2 = branch ? b2a : b2l;
        const __half* W1 = hW1t[branch];
        const __half* W2 = hW2t[branch];

        const int w    = tid >> 5;
        const int lane = tid & 31;
        const int rg   = w & 1;
        const int cg   = w >> 1;
        const int r    = lane >> 2;
        const int c2   = (lane & 3) * 2;

        const int R0 = xt * 64 + rg * 32;
        const int C0 = cg * 64;

        float acc[2][8][4];
        #pragma unroll
        for (int m = 0; m < 2; m++)
            #pragma unroll
            for (int n = 0; n < 8; n++)
                #pragma unroll
                for (int q = 0; q < 4; q++) acc[m][n][q] = 0.0f;

        // stage 1: emb @ W1 (A converted in-flight)
        #pragma unroll 4
        for (int kt = 0; kt < EMB / 16; kt++) {
            const int k0 = kt * 16;
            unsigned a[2][4];
            #pragma unroll
            for (int m = 0; m < 2; m++) {
                const float* Af = emb + (size_t)(R0 + m * 16 + r) * EMB + k0 + c2;
                a[m][0] = cvt2(*(const float2*)Af);
                a[m][1] = cvt2(*(const float2*)(Af + 8 * EMB));
                a[m][2] = cvt2(*(const float2*)(Af + 8));
                a[m][3] = cvt2(*(const float2*)(Af + 8 * EMB + 8));
            }
            #pragma unroll
            for (int n = 0; n < 8; n++) {
                const __half* Bb = W1 + (size_t)(C0 + n * 8 + r) * EMB + k0 + c2;
                unsigned b0 = *(const unsigned*)Bb;
                unsigned b1v = *(const unsigned*)(Bb + 8);
                mma16816(acc[0][n], a[0], b0, b1v);
                mma16816(acc[1][n], a[1], b0, b1v);
            }
        }

        #pragma unroll
        for (int m = 0; m < 2; m++) {
            const int lr = rg * 32 + m * 16 + r;
            #pragma unroll
            for (int n = 0; n < 8; n++) {
                const int col = C0 + n * 8 + c2;
                float2 bv = *(const float2*)(B1 + col);
                __half2 h0 = __floats2half2_rn(fmaxf(acc[m][n][0] + bv.x, 0.0f),
                                               fmaxf(acc[m][n][1] + bv.y, 0.0f));
                __half2 h1 = __floats2half2_rn(fmaxf(acc[m][n][2] + bv.x, 0.0f),
                                               fmaxf(acc[m][n][3] + bv.y, 0.0f));
                *(unsigned*)(sH + lr * SH_PITCH + col)       = *(unsigned*)&h0;
                *(unsigned*)(sH + (lr + 8) * SH_PITCH + col) = *(unsigned*)&h1;
            }
        }
        __syncthreads();

        // stage 2: H @ W2
        #pragma unroll
        for (int m = 0; m < 2; m++)
            #pragma unroll
            for (int n = 0; n < 8; n++)
                #pragma unroll
                for (int q = 0; q < 4; q++) acc[m][n][q] = 0.0f;

        #pragma unroll
        for (int kt = 0; kt < HID / 16; kt++) {
            const int k0 = kt * 16;
            unsigned a[2][4];
            #pragma unroll
            for (int m = 0; m < 2; m++) {
                const __half* Ab = sH + (rg * 32 + m * 16 + r) * SH_PITCH + k0 + c2;
                a[m][0] = *(const unsigned*)Ab;
                a[m][1] = *(const unsigned*)(Ab + 8 * SH_PITCH);
                a[m][2] = *(const unsigned*)(Ab + 8);
                a[m][3] = *(const unsigned*)(Ab + 8 * SH_PITCH + 8);
            }
            #pragma unroll
            for (int n = 0; n < 8; n++) {
                const __half* Bb = W2 + (size_t)(C0 + n * 8 + r) * HID + k0 + c2;
                unsigned b0 = *(const unsigned*)Bb;
                unsigned b1v = *(const unsigned*)(Bb + 8);
                mma16816(acc[0][n], a[0], b0, b1v);
                mma16816(acc[1][n], a[1], b0, b1v);
            }
        }

        #pragma unroll
        for (int m = 0; m < 2; m++) {
            const int row0 = R0 + m * 16 + r;
            #pragma unroll
            for (int n = 0; n < 8; n++) {
                const int col = C0 + n * 8 + c2;
                float2 bv = *(const float2*)(B2 + col);
                __half2 h0 = __floats2half2_rn(acc[m][n][0] + bv.x, acc[m][n][1] + bv.y);
                __half2 h1 = __floats2half2_rn(acc[m][n][2] + bv.x, acc[m][n][3] + bv.y);
                *(unsigned*)(g_lat + (size_t)row0 * 256 + branch * 128 + col)       = *(unsigned*)&h0;
                *(unsigned*)(g_lat + (size_t)(row0 + 8) * 256 + branch * 128 + col) = *(unsigned*)&h1;
            }
        }

        // release
        __threadfence();
        __syncthreads();
        if (tid == 0) atomicAdd(&m_done, 1u);
        return;
    }

    // =====================================================================
    // ROLE 3: edges (blocks 216..): 16 edges/block, 4/warp, interleaved lanes
    // =====================================================================
    {
        // wait for latents
        if (tid == 0) spin_wait(&m_done, MLP_BLKS);
        __syncthreads();

        const int eb = bid - TR_BLKS - MLP_BLKS;     // [0, EDGE_BLKS)

        // replay-reset ticket: last block to PASS the spin resets counters
        if (tid == 0) {
            unsigned t = atomicAdd(&e_passed, 1u);
            if (t == (unsigned)(EDGE_BLKS - 1)) {
                w_done = 0; m_done = 0; e_passed = 0;
            }
        }

        const int warp = tid >> 5;
        const int lane = tid & 31;
        const int g    = lane >> 3;
        const int s    = lane & 7;
        const int e    = eb * 16 + warp * 4 + g;

        int i, j;
        if (eb < NEG_B16) {
            i = neg_e[e]; j = neg_e[ENEG + e];
        } else if (eb < PN_B16) {
            int le = e - ENEG;
            i = pos_e[le]; j = pos_e[EPOS + le];
        } else {
            int le = e - NLOSS;
            i = pot_e[le]; j = pot_e[EPOT + le];
        }

        float aval = 0.0f, fdv = 0.0f;
        if (s == 0) {
            aval = __ldg(aa + (size_t)i * Nn + j);
            if (eb < PN_B16) fdv = __ldg(fdiff + (size_t)i * Nn + j);
        }

        const uint4* Ri = (const uint4*)(g_lat + (size_t)i * 256);
        const uint4* Rj = (const uint4*)(g_lat + (size_t)j * 256);
        uint4 u0 = Ri[s],      v0 = Rj[s];
        uint4 u1 = Ri[s + 8],  v1 = Rj[s + 8];
        uint4 u2 = Ri[s + 16], v2 = Rj[s + 16];
        uint4 u3 = Ri[s + 24], v3 = Rj[s + 24];

        float d1 = dot16h(u0, v0) + dot16h(u1, v1);
        float d2 = dot16h(u2, v2) + dot16h(u3, v3);

        d1 += __shfl_xor_sync(0xffffffffu, d1, 1);
        d2 += __shfl_xor_sync(0xffffffffu, d2, 1);
        d1 += __shfl_xor_sync(0xffffffffu, d1, 2);
        d2 += __shfl_xor_sync(0xffffffffu, d2, 2);
        d1 += __shfl_xor_sync(0xffffffffu, d1, 4);
        d2 += __shfl_xor_sync(0xffffffffu, d2, 4);

        if (s == 0) {
            float ew = emb_w[0], sw = struct_w[0];
            float lc = fsigmoid(d1);
            float ac = fsigmoid(d2 * aval);
            float vv = fsigmoid(ew * lc + sw * ac);
            if (eb >= PN_B16) {
                out[1 + e - NLOSS] = (vv < TDEL) ? 0.0f : vv;
            } else {
                float fd = fdv * (1.0f / SIGMA);
                float q = fd * fd;
                float contrib;
                if (eb >= NEG_B16) {             // positive edge
                    float e1 = vv - 1.0f;
                    contrib = __expf(-q) * e1 * e1;
                } else {                          // negative edge
                    contrib = __expf(q) * vv * vv;
                }
                atomicAdd(&g_loss[(e & 63) * 32], contrib);
                __threadfence();
            }
        }

        // folded finalize: only loss blocks participate in the ticket
        if (eb < PN_B16) {
            __syncthreads();
            if (tid == 0) {
                unsigned t = atomicAdd(&g_done, 1u);
                if (t == (unsigned)(PN_B16 - 1)) {
                    __threadfence();
                    float sum = 0.0f;
                    #pragma unroll
                    for (int q = 0; q < 64; q++) sum += g_loss[q * 32];
                    out[0] = sum * ((float)Nn / (float)NLOSS);
                    g_done = 0;
                }
            }
        }
    }
}

// ---------------------------------------------------------------------------
extern "C" void kernel_launch(void* const* d_in, const int* in_sizes, int n_in,
                              void* d_out, int out_size)
{
    const float* emb   = (const float*)d_in[0];
    const float* aa    = (const float*)d_in[1];
    const float* fdiff = (const float*)d_in[2];
    const float* W1l   = (const float*)d_in[3];
    const float* b1l   = (const float*)d_in[4];
    const float* W2l   = (const float*)d_in[5];
    const float* b2l   = (const float*)d_in[6];
    const float* W1a   = (const float*)d_in[7];
    const float* b1a   = (const float*)d_in[8];
    const float* W2a   = (const float*)d_in[9];
    const float* b2a   = (const float*)d_in[10];
    const float* emw   = (const float*)d_in[11];
    const float* stw   = (const float*)d_in[12];
    const int*   pose  = (const int*)d_in[13];
    const int*   nege  = (const int*)d_in[14];
    const int*   pote  = (const int*)d_in[15];
    float* out = (float*)d_out;

    fused_kernel<<<GRID, 128>>>(emb, aa, fdiff,
                                W1l, b1l, W2l, b2l,
                                W1a, b1a, W2a, b2a,
                                emw, stw, pose, nege, pote, out);
}

// round 14
// speedup vs baseline: 1.9634x; 1.9634x over previous
#include <cuda_runtime.h>
#include <cuda_fp16.h>

#define Nn    6144
#define EMB   256
#define HID   128
#define EPOS  98304
#define ENEG  24576
#define EPOT  262144
#define SIGMA 100.0f
#define TDEL  0.1f

#define TOT     (ENEG + EPOS + EPOT)   // 385024
#define NLOSS   (ENEG + EPOS)          // 122880

// kernel A roles
#define TR_BLKS   96                   // transpose blocks (1024 elems each)
#define MLP_BLKS  96                   // 48 row-tiles x 2 branches
// edge kernel
#define EDGE_BLKS (TOT / 64)           // 6016 (64 edges per 512-thr block)
#define NEG_B64   (ENEG / 64)          // 384
#define PN_B64    (NLOSS / 64)         // 1920

// fp16 weights (transposed, n-major)
__device__ __half hW1t[2][HID * EMB];
__device__ __half hW2t[2][HID * HID];
// latents: per node [link 0..127 | aa 128..255] = 512B
__device__ __half g_lat[Nn * 256];
// spread loss accumulators (128B stride) + counters
__device__ float g_loss[64 * 32];
__device__ unsigned w_done, g_done;    // zero at load; reset each run by finalize

// ---------------------------------------------------------------------------
__device__ __forceinline__ void mma16816(float* c, const unsigned* a,
                                         unsigned b0, unsigned b1) {
    asm volatile(
        "mma.sync.aligned.m16n8k16.row.col.f32.f16.f16.f32 "
        "{%0,%1,%2,%3}, {%4,%5,%6,%7}, {%8,%9}, {%0,%1,%2,%3};"
        : "+f"(c[0]), "+f"(c[1]), "+f"(c[2]), "+f"(c[3])
        : "r"(a[0]), "r"(a[1]), "r"(a[2]), "r"(a[3]), "r"(b0), "r"(b1));
}

__device__ __forceinline__ unsigned cvt2(float2 f) {
    __half2 h = __floats2half2_rn(f.x, f.y);
    return *(unsigned*)&h;
}

__device__ __forceinline__ float fsigmoid(float x) {
    return 1.0f / (1.0f + __expf(-x));
}

__device__ __forceinline__ float dot16h(uint4 u, uint4 v) {
    float d = 0.0f;
    float2 a, c;
    a = __half22float2(*(const __half2*)&u.x); c = __half22float2(*(const __half2*)&v.x);
    d += a.x * c.x + a.y * c.y;
    a = __half22float2(*(const __half2*)&u.y); c = __half22float2(*(const __half2*)&v.y);
    d += a.x * c.x + a.y * c.y;
    a = __half22float2(*(const __half2*)&u.z); c = __half22float2(*(const __half2*)&v.z);
    d += a.x * c.x + a.y * c.y;
    a = __half22float2(*(const __half2*)&u.w); c = __half22float2(*(const __half2*)&v.w);
    d += a.x * c.x + a.y * c.y;
    return d;
}

__device__ __forceinline__ void spin_wait(volatile unsigned* p, unsigned target) {
    while (*p < target) __nanosleep(100);
    __threadfence();   // acquire
}

#define SH_PITCH 136   // padded half pitch

// ===========================================================================
// Kernel A: transpose (blocks 0..95) + MLP (blocks 96..191), 256 threads.
// Small grid -> everything wave-1 resident; spin is deadlock-free.
// ===========================================================================
__global__ __launch_bounds__(256) void prepmlp_kernel(
    const float* __restrict__ emb,
    const float* __restrict__ W1l, const float* __restrict__ b1l,
    const float* __restrict__ W2l, const float* __restrict__ b2l,
    const float* __restrict__ W1a, const float* __restrict__ b1a,
    const float* __restrict__ W2a, const float* __restrict__ b2a)
{
    __shared__ __half sH[128 * SH_PITCH];   // 34816 B (used by MLP role only)
    const int bid = blockIdx.x;
    const int tid = threadIdx.x;

    // ----------------- ROLE 1: weight transpose (96 blocks) -----------------
    if (bid < TR_BLKS) {
        if (bid == 0 && tid < 64) g_loss[tid * 32] = 0.0f;

        #pragma unroll
        for (int t = 0; t < 4; t++) {
            int widx = bid * 1024 + t * 256 + tid;     // [0, 98304)
            if (widx < 2 * EMB * HID) {                // W1 transposes
                int br = widx >> 15;
                int r  = widx & 32767;
                int k  = r >> 7, n = r & 127;
                const float* W = br ? W1a : W1l;
                hW1t[br][n * EMB + k] = __float2half(W[k * HID + n]);
            } else {
                int t2 = widx - 2 * EMB * HID;
                int br = t2 >> 14;
                int r  = t2 & 16383;
                int k  = r >> 7, n = r & 127;
                const float* W = br ? W2a : W2l;
                hW2t[br][n * HID + k] = __float2half(W[k * HID + n]);
            }
        }

        __threadfence();
        __syncthreads();
        if (tid == 0) atomicAdd(&w_done, 1u);
        return;
    }

    // ----------------- ROLE 2: MLP, 128 rows x 128 cols per block -----------
    if (tid == 0) spin_wait(&w_done, TR_BLKS);
    __syncthreads();

    const int mb = bid - TR_BLKS;
    const int branch = mb & 1;
    const int xt = mb >> 1;                 // 0..47
    const float* B1 = branch ? b1a : b1l;
    const float* B2 = branch ? b2a : b2l;
    const __half* W1 = hW1t[branch];
    const __half* W2 = hW2t[branch];

    const int w    = tid >> 5;              // 0..7
    const int lane = tid & 31;
    const int rg   = w & 3;                 // 4 rowgroups of 32
    const int cg   = w >> 2;                // 2 colgroups of 64
    const int r    = lane >> 2;
    const int c2   = (lane & 3) * 2;

    const int R0 = xt * 128 + rg * 32;
    const int C0 = cg * 64;

    float acc[2][8][4];
    #pragma unroll
    for (int m = 0; m < 2; m++)
        #pragma unroll
        for (int n = 0; n < 8; n++)
            #pragma unroll
            for (int q = 0; q < 4; q++) acc[m][n][q] = 0.0f;

    // stage 1: emb @ W1 (A converted fp32->fp16 in flight)
    #pragma unroll 4
    for (int kt = 0; kt < EMB / 16; kt++) {
        const int k0 = kt * 16;
        unsigned a[2][4];
        #pragma unroll
        for (int m = 0; m < 2; m++) {
            const float* Af = emb + (size_t)(R0 + m * 16 + r) * EMB + k0 + c2;
            a[m][0] = cvt2(*(const float2*)Af);
            a[m][1] = cvt2(*(const float2*)(Af + 8 * EMB));
            a[m][2] = cvt2(*(const float2*)(Af + 8));
            a[m][3] = cvt2(*(const float2*)(Af + 8 * EMB + 8));
        }
        #pragma unroll
        for (int n = 0; n < 8; n++) {
            const __half* Bb = W1 + (size_t)(C0 + n * 8 + r) * EMB + k0 + c2;
            unsigned b0 = *(const unsigned*)Bb;
            unsigned b1v = *(const unsigned*)(Bb + 8);
            mma16816(acc[0][n], a[0], b0, b1v);
            mma16816(acc[1][n], a[1], b0, b1v);
        }
    }

    #pragma unroll
    for (int m = 0; m < 2; m++) {
        const int lr = rg * 32 + m * 16 + r;
        #pragma unroll
        for (int n = 0; n < 8; n++) {
            const int col = C0 + n * 8 + c2;
            float2 bv = *(const float2*)(B1 + col);
            __half2 h0 = __floats2half2_rn(fmaxf(acc[m][n][0] + bv.x, 0.0f),
                                           fmaxf(acc[m][n][1] + bv.y, 0.0f));
            __half2 h1 = __floats2half2_rn(fmaxf(acc[m][n][2] + bv.x, 0.0f),
                                           fmaxf(acc[m][n][3] + bv.y, 0.0f));
            *(unsigned*)(sH + lr * SH_PITCH + col)       = *(unsigned*)&h0;
            *(unsigned*)(sH + (lr + 8) * SH_PITCH + col) = *(unsigned*)&h1;
        }
    }
    __syncthreads();

    // stage 2: H @ W2
    #pragma unroll
    for (int m = 0; m < 2; m++)
        #pragma unroll
        for (int n = 0; n < 8; n++)
            #pragma unroll
            for (int q = 0; q < 4; q++) acc[m][n][q] = 0.0f;

    #pragma unroll
    for (int kt = 0; kt < HID / 16; kt++) {
        const int k0 = kt * 16;
        unsigned a[2][4];
        #pragma unroll
        for (int m = 0; m < 2; m++) {
            const __half* Ab = sH + (rg * 32 + m * 16 + r) * SH_PITCH + k0 + c2;
            a[m][0] = *(const unsigned*)Ab;
            a[m][1] = *(const unsigned*)(Ab + 8 * SH_PITCH);
            a[m][2] = *(const unsigned*)(Ab + 8);
            a[m][3] = *(const unsigned*)(Ab + 8 * SH_PITCH + 8);
        }
        #pragma unroll
        for (int n = 0; n < 8; n++) {
            const __half* Bb = W2 + (size_t)(C0 + n * 8 + r) * HID + k0 + c2;
            unsigned b0 = *(const unsigned*)Bb;
            unsigned b1v = *(const unsigned*)(Bb + 8);
            mma16816(acc[0][n], a[0], b0, b1v);
            mma16816(acc[1][n], a[1], b0, b1v);
        }
    }

    #pragma unroll
    for (int m = 0; m < 2; m++) {
        const int row0 = R0 + m * 16 + r;
        #pragma unroll
        for (int n = 0; n < 8; n++) {
            const int col = C0 + n * 8 + c2;
            float2 bv = *(const float2*)(B2 + col);
            __half2 h0 = __floats2half2_rn(acc[m][n][0] + bv.x, acc[m][n][1] + bv.y);
            __half2 h1 = __floats2half2_rn(acc[m][n][2] + bv.x, acc[m][n][3] + bv.y);
            *(unsigned*)(g_lat + (size_t)row0 * 256 + branch * 128 + col)       = *(unsigned*)&h0;
            *(unsigned*)(g_lat + (size_t)(row0 + 8) * 256 + branch * 128 + col) = *(unsigned*)&h1;
        }
    }
}

// ===========================================================================
// Edge kernel: 512 threads, 64 edges/block (4 per warp, interleaved lanes).
// Loss blocks [0, PN_B64) run the finalize ticket; pot blocks skip it.
// ===========================================================================
__global__ __launch_bounds__(512) void edge_kernel(
    const float* __restrict__ aa,
    const float* __restrict__ fdiff,
    const int*   __restrict__ pos_e,
    const int*   __restrict__ neg_e,
    const int*   __restrict__ pot_e,
    const float* __restrict__ emb_w,
    const float* __restrict__ struct_w,
    float* __restrict__ out)
{
    const int b    = blockIdx.x;
    const int tid  = threadIdx.x;
    const int warp = tid >> 5;        // 0..15
    const int lane = tid & 31;
    const int g    = lane >> 3;       // edge within warp (0..3)
    const int s    = lane & 7;        // sub-lane within 8-lane group
    const int e    = b * 64 + warp * 4 + g;

    int i, j;
    if (b < NEG_B64) {
        i = neg_e[e]; j = neg_e[ENEG + e];
    } else if (b < PN_B64) {
        int le = e - ENEG;
        i = pos_e[le]; j = pos_e[EPOS + le];
    } else {
        int le = e - NLOSS;
        i = pot_e[le]; j = pot_e[EPOT + le];
    }

    // early DRAM gathers by the leader lane — overlap with the dot work below
    float aval = 0.0f, fdv = 0.0f;
    if (s == 0) {
        aval = __ldg(aa + (size_t)i * Nn + j);
        if (b < PN_B64) fdv = __ldg(fdiff + (size_t)i * Nn + j);
    }

    // interleaved loads: idx 0..15 = link half, 16..31 = aa half
    const uint4* Ri = (const uint4*)(g_lat + (size_t)i * 256);
    const uint4* Rj = (const uint4*)(g_lat + (size_t)j * 256);
    uint4 u0 = Ri[s],      v0 = Rj[s];
    uint4 u1 = Ri[s + 8],  v1 = Rj[s + 8];
    uint4 u2 = Ri[s + 16], v2 = Rj[s + 16];
    uint4 u3 = Ri[s + 24], v3 = Rj[s + 24];

    float d1 = dot16h(u0, v0) + dot16h(u1, v1);   // link dot partial
    float d2 = dot16h(u2, v2) + dot16h(u3, v3);   // aa dot partial

    d1 += __shfl_xor_sync(0xffffffffu, d1, 1);
    d2 += __shfl_xor_sync(0xffffffffu, d2, 1);
    d1 += __shfl_xor_sync(0xffffffffu, d1, 2);
    d2 += __shfl_xor_sync(0xffffffffu, d2, 2);
    d1 += __shfl_xor_sync(0xffffffffu, d1, 4);
    d2 += __shfl_xor_sync(0xffffffffu, d2, 4);

    if (s == 0) {
        float ew = emb_w[0], sw = struct_w[0];
        float lc = fsigmoid(d1);
        float ac = fsigmoid(d2 * aval);
        float vv = fsigmoid(ew * lc + sw * ac);
        if (b >= PN_B64) {
            out[1 + e - NLOSS] = (vv < TDEL) ? 0.0f : vv;
        } else {
            float fd = fdv * (1.0f / SIGMA);
            float q = fd * fd;
            float contrib;
            if (b >= NEG_B64) {              // positive edge
                float e1 = vv - 1.0f;
                contrib = __expf(-q) * e1 * e1;
            } else {                          // negative edge
                contrib = __expf(q) * vv * vv;
            }
            atomicAdd(&g_loss[(e & 63) * 32], contrib);
            __threadfence();                  // visible before ticket
        }
    }

    // folded finalize: only loss blocks participate in the ticket
    if (b < PN_B64) {
        __syncthreads();
        if (tid == 0) {
            unsigned t = atomicAdd(&g_done, 1u);
            if (t == (unsigned)(PN_B64 - 1)) {
                __threadfence();
                float sum = 0.0f;
                #pragma unroll
                for (int q = 0; q < 64; q++) sum += g_loss[q * 32];
                out[0] = sum * ((float)Nn / (float)NLOSS);
                g_done = 0;                   // reset for next graph replay
                w_done = 0;                   // reset kernel-A dependency flag
            }
        }
    }
}

// ---------------------------------------------------------------------------
extern "C" void kernel_launch(void* const* d_in, const int* in_sizes, int n_in,
                              void* d_out, int out_size)
{
    const float* emb   = (const float*)d_in[0];
    const float* aa    = (const float*)d_in[1];
    const float* fdiff = (const float*)d_in[2];
    const float* W1l   = (const float*)d_in[3];
    const float* b1l   = (const float*)d_in[4];
    const float* W2l   = (const float*)d_in[5];
    const float* b2l   = (const float*)d_in[6];
    const float* W1a   = (const float*)d_in[7];
    const float* b1a   = (const float*)d_in[8];
    const float* W2a   = (const float*)d_in[9];
    const float* b2a   = (const float*)d_in[10];
    const float* emw   = (const float*)d_in[11];
    const float* stw   = (const float*)d_in[12];
    const int*   pose  = (const int*)d_in[13];
    const int*   nege  = (const int*)d_in[14];
    const int*   pote  = (const int*)d_in[15];
    float* out = (float*)d_out;

    prepmlp_kernel<<<TR_BLKS + MLP_BLKS, 256>>>(emb, W1l, b1l, W2l, b2l,
                                                W1a, b1a, W2a, b2a);

    edge_kernel<<<EDGE_BLKS, 512>>>(aa, fdiff, pose, nege, pote, emw, stw, out);
}

// round 15
// speedup vs baseline: 2.0946x; 1.0668x over previous
#include <cuda_runtime.h>
#include <cuda_fp16.h>

#define Nn    6144
#define EMB   256
#define HID   128
#define EPOS  98304
#define ENEG  24576
#define EPOT  262144
#define SIGMA 100.0f
#define TDEL  0.1f

#define TOT     (ENEG + EPOS + EPOT)   // 385024
#define NLOSS   (ENEG + EPOS)          // 122880

// kernel A roles
#define TR_BLKS   96                   // transpose blocks (1024 elems each)
#define MLP_BLKS  96                   // 48 row-tiles x 2 branches
// edge kernel
#define EDGE_BLKS (TOT / 64)           // 6016 (64 edges per 512-thr block)
#define NEG_B64   (ENEG / 64)          // 384
#define PN_B64    (NLOSS / 64)         // 1920

// fp16 weights (transposed, n-major)
__device__ __half hW1t[2][HID * EMB];
__device__ __half hW2t[2][HID * HID];
// latents: per node [link 0..127 | aa 128..255] = 512B
__device__ __half g_lat[Nn * 256];
// spread loss accumulators (128B stride) + counters
__device__ float g_loss[64 * 32];
__device__ unsigned w_done, g_done;    // zero at load; reset each run

// ---------------------------------------------------------------------------
__device__ __forceinline__ void mma16816(float* c, const unsigned* a,
                                         unsigned b0, unsigned b1) {
    asm volatile(
        "mma.sync.aligned.m16n8k16.row.col.f32.f16.f16.f32 "
        "{%0,%1,%2,%3}, {%4,%5,%6,%7}, {%8,%9}, {%0,%1,%2,%3};"
        : "+f"(c[0]), "+f"(c[1]), "+f"(c[2]), "+f"(c[3])
        : "r"(a[0]), "r"(a[1]), "r"(a[2]), "r"(a[3]), "r"(b0), "r"(b1));
}

__device__ __forceinline__ unsigned cvt2(float2 f) {
    __half2 h = __floats2half2_rn(f.x, f.y);
    return *(unsigned*)&h;
}

__device__ __forceinline__ float fsigmoid(float x) {
    return 1.0f / (1.0f + __expf(-x));
}

// fp16 HFMA2 chain over one uint4 pair (8 halves): 4 packed ops + 1 convert
__device__ __forceinline__ float2 dotchain(uint4 u, uint4 v) {
    __half2 acc = __hmul2(*(const __half2*)&u.x, *(const __half2*)&v.x);
    acc = __hfma2(*(const __half2*)&u.y, *(const __half2*)&v.y, acc);
    acc = __hfma2(*(const __half2*)&u.z, *(const __half2*)&v.z, acc);
    acc = __hfma2(*(const __half2*)&u.w, *(const __half2*)&v.w, acc);
    return __half22float2(acc);
}

__device__ __forceinline__ void spin_wait(volatile unsigned* p, unsigned target) {
    while (*p < target) __nanosleep(100);
    __threadfence();   // acquire
}

#define SH_PITCH 136   // padded half pitch

// ===========================================================================
// Kernel A: transpose (blocks 0..95) + MLP (blocks 96..191), 256 threads.
// ===========================================================================
__global__ __launch_bounds__(256) void prepmlp_kernel(
    const float* __restrict__ emb,
    const float* __restrict__ W1l, const float* __restrict__ b1l,
    const float* __restrict__ W2l, const float* __restrict__ b2l,
    const float* __restrict__ W1a, const float* __restrict__ b1a,
    const float* __restrict__ W2a, const float* __restrict__ b2a)
{
    __shared__ __half sH[128 * SH_PITCH];   // 34816 B (MLP role only)
    const int bid = blockIdx.x;
    const int tid = threadIdx.x;

    // ----------------- ROLE 1: weight transpose (96 blocks) -----------------
    if (bid < TR_BLKS) {
        if (bid == 0 && tid < 64) g_loss[tid * 32] = 0.0f;

        #pragma unroll
        for (int t = 0; t < 4; t++) {
            int widx = bid * 1024 + t * 256 + tid;     // [0, 98304)
            if (widx < 2 * EMB * HID) {                // W1 transposes
                int br = widx >> 15;
                int r  = widx & 32767;
                int k  = r >> 7, n = r & 127;
                const float* W = br ? W1a : W1l;
                hW1t[br][n * EMB + k] = __float2half(W[k * HID + n]);
            } else {
                int t2 = widx - 2 * EMB * HID;
                int br = t2 >> 14;
                int r  = t2 & 16383;
                int k  = r >> 7, n = r & 127;
                const float* W = br ? W2a : W2l;
                hW2t[br][n * HID + k] = __float2half(W[k * HID + n]);
            }
        }

        __threadfence();
        __syncthreads();
        if (tid == 0) atomicAdd(&w_done, 1u);
        return;
    }

    // ----------------- ROLE 2: MLP, 128 rows x 128 cols per block -----------
    if (tid == 0) spin_wait(&w_done, TR_BLKS);
    __syncthreads();

    const int mb = bid - TR_BLKS;
    const int branch = mb & 1;
    const int xt = mb >> 1;                 // 0..47
    const float* B1 = branch ? b1a : b1l;
    const float* B2 = branch ? b2a : b2l;
    const __half* W1 = hW1t[branch];
    const __half* W2 = hW2t[branch];

    const int w    = tid >> 5;              // 0..7
    const int lane = tid & 31;
    const int rg   = w & 3;                 // 4 rowgroups of 32
    const int cg   = w >> 2;                // 2 colgroups of 64
    const int r    = lane >> 2;
    const int c2   = (lane & 3) * 2;

    const int R0 = xt * 128 + rg * 32;
    const int C0 = cg * 64;

    float acc[2][8][4];
    #pragma unroll
    for (int m = 0; m < 2; m++)
        #pragma unroll
        for (int n = 0; n < 8; n++)
            #pragma unroll
            for (int q = 0; q < 4; q++) acc[m][n][q] = 0.0f;

    // stage 1: emb @ W1 (A converted fp32->fp16 in flight)
    #pragma unroll 4
    for (int kt = 0; kt < EMB / 16; kt++) {
        const int k0 = kt * 16;
        unsigned a[2][4];
        #pragma unroll
        for (int m = 0; m < 2; m++) {
            const float* Af = emb + (size_t)(R0 + m * 16 + r) * EMB + k0 + c2;
            a[m][0] = cvt2(*(const float2*)Af);
            a[m][1] = cvt2(*(const float2*)(Af + 8 * EMB));
            a[m][2] = cvt2(*(const float2*)(Af + 8));
            a[m][3] = cvt2(*(const float2*)(Af + 8 * EMB + 8));
        }
        #pragma unroll
        for (int n = 0; n < 8; n++) {
            const __half* Bb = W1 + (size_t)(C0 + n * 8 + r) * EMB + k0 + c2;
            unsigned b0 = *(const unsigned*)Bb;
            unsigned b1v = *(const unsigned*)(Bb + 8);
            mma16816(acc[0][n], a[0], b0, b1v);
            mma16816(acc[1][n], a[1], b0, b1v);
        }
    }

    #pragma unroll
    for (int m = 0; m < 2; m++) {
        const int lr = rg * 32 + m * 16 + r;
        #pragma unroll
        for (int n = 0; n < 8; n++) {
            const int col = C0 + n * 8 + c2;
            float2 bv = *(const float2*)(B1 + col);
            __half2 h0 = __floats2half2_rn(fmaxf(acc[m][n][0] + bv.x, 0.0f),
                                           fmaxf(acc[m][n][1] + bv.y, 0.0f));
            __half2 h1 = __floats2half2_rn(fmaxf(acc[m][n][2] + bv.x, 0.0f),
                                           fmaxf(acc[m][n][3] + bv.y, 0.0f));
            *(unsigned*)(sH + lr * SH_PITCH + col)       = *(unsigned*)&h0;
            *(unsigned*)(sH + (lr + 8) * SH_PITCH + col) = *(unsigned*)&h1;
        }
    }
    __syncthreads();

    // stage 2: H @ W2
    #pragma unroll
    for (int m = 0; m < 2; m++)
        #pragma unroll
        for (int n = 0; n < 8; n++)
            #pragma unroll
            for (int q = 0; q < 4; q++) acc[m][n][q] = 0.0f;

    #pragma unroll
    for (int kt = 0; kt < HID / 16; kt++) {
        const int k0 = kt * 16;
        unsigned a[2][4];
        #pragma unroll
        for (int m = 0; m < 2; m++) {
            const __half* Ab = sH + (rg * 32 + m * 16 + r) * SH_PITCH + k0 + c2;
            a[m][0] = *(const unsigned*)Ab;
            a[m][1] = *(const unsigned*)(Ab + 8 * SH_PITCH);
            a[m][2] = *(const unsigned*)(Ab + 8);
            a[m][3] = *(const unsigned*)(Ab + 8 * SH_PITCH + 8);
        }
        #pragma unroll
        for (int n = 0; n < 8; n++) {
            const __half* Bb = W2 + (size_t)(C0 + n * 8 + r) * HID + k0 + c2;
            unsigned b0 = *(const unsigned*)Bb;
            unsigned b1v = *(const unsigned*)(Bb + 8);
            mma16816(acc[0][n], a[0], b0, b1v);
            mma16816(acc[1][n], a[1], b0, b1v);
        }
    }

    #pragma unroll
    for (int m = 0; m < 2; m++) {
        const int row0 = R0 + m * 16 + r;
        #pragma unroll
        for (int n = 0; n < 8; n++) {
            const int col = C0 + n * 8 + c2;
            float2 bv = *(const float2*)(B2 + col);
            __half2 h0 = __floats2half2_rn(acc[m][n][0] + bv.x, acc[m][n][1] + bv.y);
            __half2 h1 = __floats2half2_rn(acc[m][n][2] + bv.x, acc[m][n][3] + bv.y);
            *(unsigned*)(g_lat + (size_t)row0 * 256 + branch * 128 + col)       = *(unsigned*)&h0;
            *(unsigned*)(g_lat + (size_t)(row0 + 8) * 256 + branch * 128 + col) = *(unsigned*)&h1;
        }
    }
}

// ===========================================================================
// Edge kernel: 512 threads, 64 edges/block (4 per warp, interleaved lanes).
// Dot products via packed HFMA2 chains (4 fp16 products per chain, fp32 combine).
// ===========================================================================
__global__ __launch_bounds__(512, 4) void edge_kernel(
    const float* __restrict__ aa,
    const float* __restrict__ fdiff,
    const int*   __restrict__ pos_e,
    const int*   __restrict__ neg_e,
    const int*   __restrict__ pot_e,
    const float* __restrict__ emb_w,
    const float* __restrict__ struct_w,
    float* __restrict__ out)
{
    const int b    = blockIdx.x;
    const int tid  = threadIdx.x;
    const int warp = tid >> 5;        // 0..15
    const int lane = tid & 31;
    const int g    = lane >> 3;       // edge within warp (0..3)
    const int s    = lane & 7;        // sub-lane within 8-lane group
    const int e    = b * 64 + warp * 4 + g;

    int i, j;
    if (b < NEG_B64) {
        i = neg_e[e]; j = neg_e[ENEG + e];
    } else if (b < PN_B64) {
        int le = e - ENEG;
        i = pos_e[le]; j = pos_e[EPOS + le];
    } else {
        int le = e - NLOSS;
        i = pot_e[le]; j = pot_e[EPOT + le];
    }

    // early DRAM gathers by the leader lane — overlap with the dot work below
    float aval = 0.0f, fdv = 0.0f;
    if (s == 0) {
        aval = __ldg(aa + (size_t)i * Nn + j);
        if (b < PN_B64) fdv = __ldg(fdiff + (size_t)i * Nn + j);
    }

    // interleaved loads: idx 0..15 = link half, 16..31 = aa half
    const uint4* Ri = (const uint4*)(g_lat + (size_t)i * 256);
    const uint4* Rj = (const uint4*)(g_lat + (size_t)j * 256);
    uint4 u0 = Ri[s],      v0 = Rj[s];
    uint4 u1 = Ri[s + 8],  v1 = Rj[s + 8];
    uint4 u2 = Ri[s + 16], v2 = Rj[s + 16];
    uint4 u3 = Ri[s + 24], v3 = Rj[s + 24];

    float2 p0 = dotchain(u0, v0);
    float2 p1 = dotchain(u1, v1);
    float2 p2 = dotchain(u2, v2);
    float2 p3 = dotchain(u3, v3);
    float d1 = (p0.x + p0.y) + (p1.x + p1.y);   // link dot partial
    float d2 = (p2.x + p2.y) + (p3.x + p3.y);   // aa dot partial

    d1 += __shfl_xor_sync(0xffffffffu, d1, 1);
    d2 += __shfl_xor_sync(0xffffffffu, d2, 1);
    d1 += __shfl_xor_sync(0xffffffffu, d1, 2);
    d2 += __shfl_xor_sync(0xffffffffu, d2, 2);
    d1 += __shfl_xor_sync(0xffffffffu, d1, 4);
    d2 += __shfl_xor_sync(0xffffffffu, d2, 4);

    if (s == 0) {
        float ew = emb_w[0], sw = struct_w[0];
        float lc = fsigmoid(d1);
        float ac = fsigmoid(d2 * aval);
        float vv = fsigmoid(ew * lc + sw * ac);
        if (b >= PN_B64) {
            out[1 + e - NLOSS] = (vv < TDEL) ? 0.0f : vv;
        } else {
            float fd = fdv * (1.0f / SIGMA);
            float q = fd * fd;
            float contrib;
            if (b >= NEG_B64) {              // positive edge
                float e1 = vv - 1.0f;
                contrib = __expf(-q) * e1 * e1;
            } else {                          // negative edge
                contrib = __expf(q) * vv * vv;
            }
            atomicAdd(&g_loss[(e & 63) * 32], contrib);
            __threadfence();                  // visible before ticket
        }
    }

    // folded finalize: only loss blocks participate in the ticket
    if (b < PN_B64) {
        __syncthreads();
        if (tid == 0) {
            unsigned t = atomicAdd(&g_done, 1u);
            if (t == (unsigned)(PN_B64 - 1)) {
                __threadfence();
                float sum = 0.0f;
                #pragma unroll
                for (int q = 0; q < 64; q++) sum += g_loss[q * 32];
                out[0] = sum * ((float)Nn / (float)NLOSS);
                g_done = 0;                   // reset for next graph replay
                w_done = 0;                   // reset kernel-A dependency flag
            }
        }
    }
}

// ---------------------------------------------------------------------------
extern "C" void kernel_launch(void* const* d_in, const int* in_sizes, int n_in,
                              void* d_out, int out_size)
{
    const float* emb   = (const float*)d_in[0];
    const float* aa    = (const float*)d_in[1];
    const float* fdiff = (const float*)d_in[2];
    const float* W1l   = (const float*)d_in[3];
    const float* b1l   = (const float*)d_in[4];
    const float* W2l   = (const float*)d_in[5];
    const float* b2l   = (const float*)d_in[6];
    const float* W1a   = (const float*)d_in[7];
    const float* b1a   = (const float*)d_in[8];
    const float* W2a   = (const float*)d_in[9];
    const float* b2a   = (const float*)d_in[10];
    const float* emw   = (const float*)d_in[11];
    const float* stw   = (const float*)d_in[12];
    const int*   pose  = (const int*)d_in[13];
    const int*   nege  = (const int*)d_in[14];
    const int*   pote  = (const int*)d_in[15];
    float* out = (float*)d_out;

    prepmlp_kernel<<<TR_BLKS + MLP_BLKS, 256>>>(emb, W1l, b1l, W2l, b2l,
                                                W1a, b1a, W2a, b2a);

    edge_kernel<<<EDGE_BLKS, 512>>>(aa, fdiff, pose, nege, pote, emw, stw, out);
}